// round 5
// baseline (speedup 1.0000x reference)
#include <cuda_runtime.h>
#include <cstdint>
#include <utility>

// ============================================================================
// Compile-time structure builder. Reproduces the reference enumeration exactly
// (to recover each term's original index into CG_vals), then re-sorts terms:
//   major: m_total = m1+m2  (7 groups, -3..3)
//   mid:   (M1, M2) pair    (pair products factorized)
//   minor: l (output degree) -> accumulator slot l - |m|
// The shared cgw table is indexed by SORTED position so the inner loop reads
// consecutive addresses (LDS.128 pairs).
// ============================================================================
namespace wtp {

constexpr int LMAX = 3;
constexpr int MOUT = 16;
constexpr int NNZ  = 478;
constexpr int C    = 128;
constexpr int NCHP = 8;         // channel-pairs per block (16 channels)
constexpr int NSLOT = 8;        // row slots per block
constexpr int RPT  = 2;         // rows per thread
constexpr int NROWB = NSLOT * RPT;       // 16 rows per block
constexpr int NTHREADS = NCHP * NSLOT;   // 64
constexpr int NGRP = 7;

struct Structure {
    int m1[NNZ];
    int m2[NNZ];
    int aidx[NNZ];
    int orig[NNZ];      // reference-order index feeding sorted slot t
    bool newpair[NNZ];
    int start[NGRP + 1];
    int count;
};

constexpr Structure build_structure() {
    Structure s{};
    int tl[64] = {}, tl1[64] = {}, tl2[64] = {};
    int nt = 0;
    for (int l1 = 0; l1 <= LMAX; l1++)
        for (int l2 = 0; l2 <= LMAX; l2++) {
            int lo = (l1 > l2) ? (l1 - l2) : (l2 - l1);
            int hi = (l1 + l2 < LMAX) ? (l1 + l2) : LMAX;
            for (int l = lo; l <= hi; l++) { tl[nt]=l; tl1[nt]=l1; tl2[nt]=l2; nt++; }
        }
    int rm1[NNZ]={}, rm2[NNZ]={}, rl[NNZ]={}, rm[NNZ]={};
    int cnt = 0;
    for (int l = 0; l <= LMAX; l++)
        for (int m = -l; m <= l; m++) {
            for (int t = 0; t < nt; t++) {
                if (tl[t] != l) continue;
                int l1 = tl1[t], l2 = tl2[t];
                int lo = (-l1 > m - l2) ? -l1 : (m - l2);
                int hi = (l1 < m + l2) ? l1 : (m + l2);
                for (int m1 = lo; m1 <= hi; m1++) {
                    int m2 = m - m1;
                    rm1[cnt] = l1*l1 + l1 + m1;
                    rm2[cnt] = l2*l2 + l2 + m2;
                    rl[cnt]  = l;
                    rm[cnt]  = m;
                    cnt++;
                }
            }
        }
    s.count = cnt;
    int key[NNZ] = {};
    for (int i = 0; i < cnt; i++)
        key[i] = (((rm[i] + 3) * 16 + rm1[i]) * 16 + rm2[i]) * 4 + rl[i];
    int sm[NNZ] = {};
    for (int i = 0; i < cnt; i++) {
        int rank = 0;
        for (int j = 0; j < cnt; j++)
            if (key[j] < key[i] || (key[j] == key[i] && j < i)) rank++;
        int am = rm[i] < 0 ? -rm[i] : rm[i];
        s.m1[rank]   = rm1[i];
        s.m2[rank]   = rm2[i];
        s.aidx[rank] = rl[i] - am;
        s.orig[rank] = i;
        sm[rank]     = rm[i];
    }
    for (int i = 0; i < cnt; i++)
        s.newpair[i] = (i == 0) || (s.m1[i] != s.m1[i-1]) || (s.m2[i] != s.m2[i-1]);
    for (int g = 0; g <= NGRP; g++) {
        int st = cnt;
        for (int i = 0; i < cnt; i++)
            if (sm[i] + 3 >= g) { st = i; break; }
        s.start[g] = st;
    }
    return s;
}

constexpr Structure S = build_structure();
static_assert(S.count == NNZ, "term count mismatch vs reference structure");
static_assert(S.start[0] == 0 && S.start[NGRP] == NNZ, "group partition broken");

// inverse map: sorted slot for each original index; must live in device-visible
// memory because the cgw build loop indexes it with a RUNTIME term index.
struct Inv { int slot[NNZ]; };
constexpr Inv build_inv() {
    Inv v{};
    for (int t = 0; t < NNZ; t++) v.slot[S.orig[t]] = t;
    return v;
}
__constant__ Inv INV_c = build_inv();   // constexpr-initialized constant memory

} // namespace wtp

using ull = unsigned long long;

// ============================================================================
// Per-term executor with PRELOADED wv (keeps LDS out of this path so pairs of
// terms share one LDS.128). Packed f32x2 math, 2 rows per thread.
// ============================================================================
template <int T>
__device__ __forceinline__ void do_term_wv(
    const ull wv,
    const ull (&X1)[wtp::RPT][wtp::MOUT],
    const ull (&X2)[wtp::RPT][wtp::MOUT],
    ull (&ACC)[wtp::RPT][4],
    ull (&p)[wtp::RPT])
{
    constexpr int m1 = wtp::S.m1[T];
    constexpr int m2 = wtp::S.m2[T];
    constexpr int ai = wtp::S.aidx[T];
    if constexpr (wtp::S.newpair[T]) {
        asm("mul.rn.f32x2 %0, %1, %2;" : "=l"(p[0]) : "l"(X1[0][m1]), "l"(X2[0][m2]));
        asm("mul.rn.f32x2 %0, %1, %2;" : "=l"(p[1]) : "l"(X1[1][m1]), "l"(X2[1][m2]));
    }
    asm("fma.rn.f32x2 %0, %1, %2, %3;" : "=l"(ACC[0][ai]) : "l"(p[0]), "l"(wv), "l"(ACC[0][ai]));
    asm("fma.rn.f32x2 %0, %1, %2, %3;" : "=l"(ACC[1][ai]) : "l"(p[1]), "l"(wv), "l"(ACC[1][ai]));
}

// Pairs: one 16-byte LDS feeds two consecutive sorted terms.
template <int PB, int... Is>
__device__ __forceinline__ void run_pairs(
    std::integer_sequence<int, Is...>,
    const ull* __restrict__ cgw_tp,
    const ull (&X1)[wtp::RPT][wtp::MOUT],
    const ull (&X2)[wtp::RPT][wtp::MOUT],
    ull (&ACC)[wtp::RPT][4],
    ull (&p)[wtp::RPT])
{
    (([&] {
        const ulonglong2 wv2 =
            *reinterpret_cast<const ulonglong2*>(cgw_tp + PB + 2 * Is);
        do_term_wv<PB + 2 * Is>(wv2.x, X1, X2, ACC, p);
        do_term_wv<PB + 2 * Is + 1>(wv2.y, X1, X2, ACC, p);
    }()), ...);
}

template <int G>
__device__ __forceinline__ void run_group(
    const ull* __restrict__ cgw_tp,
    const ull (&X1)[wtp::RPT][wtp::MOUT],
    const ull (&X2)[wtp::RPT][wtp::MOUT],
    ull* __restrict__ op0,
    ull* __restrict__ op1)
{
    constexpr int m  = G - 3;
    constexpr int la = m < 0 ? -m : m;
    constexpr int ns = 4 - la;
    constexpr int nb = wtp::S.start[G];
    constexpr int ne = wtp::S.start[G + 1];
    constexpr int first = (nb & 1) ? nb + 1 : nb;   // 16B-aligned pair base
    constexpr int npair = (ne - first) / 2;
    constexpr int tail  = first + 2 * npair;        // == ne or ne-1

    ull ACC[wtp::RPT][4] = {};
    ull p[wtp::RPT] = {};

    if constexpr (nb & 1)
        do_term_wv<nb>(cgw_tp[nb], X1, X2, ACC, p);
    run_pairs<first>(std::make_integer_sequence<int, npair>{}, cgw_tp, X1, X2, ACC, p);
    if constexpr (tail < ne)
        do_term_wv<tail>(cgw_tp[tail], X1, X2, ACC, p);

    #pragma unroll
    for (int i = 0; i < ns; i++) {
        constexpr int CC = wtp::C / 2;
        const int l = la + i;
        op0[(l * l + l + m) * CC] = ACC[0][i];
        op1[(l * l + l + m) * CC] = ACC[1][i];
    }
}

// ============================================================================
// Kernel. Block = 64 threads = 8 ch-pairs x 8 row-slots, RPT=2 -> 16 rows x
// 16 channels per block. Grid = 1024 (fine-grained -> balanced waves).
// Shared cgw laid out [cp][sorted_term]: stride 478 ull = 3824 B per cp
// (16B-aligned, cp lanes land on distinct banks: 956 mod 32 = 28).
// ============================================================================
__global__ void __launch_bounds__(wtp::NTHREADS, 6)
wtp_kernel(const float* __restrict__ x1,
           const float* __restrict__ x2,
           const float* __restrict__ w,
           const float* __restrict__ cg,
           const int*   __restrict__ l_ind,
           float* __restrict__ out)
{
    extern __shared__ ull cgw_s[];  // [NCHP][NNZ] packed f32x2, sorted order

    const int tid     = threadIdx.x;
    const int cgroup  = blockIdx.x & 7;                  // 8 groups of 16 channels
    const int rowbase = (blockIdx.x >> 3) * wtp::NROWB;  // 16 rows per block
    const int cp      = tid & (wtp::NCHP - 1);
    const int rs      = tid >> 3;                        // 0..7
    const int cbase   = cgroup * 16;

    // --- per-block CG*weight table, re-indexed to sorted term order ---
    {
        float2* cgw_f = reinterpret_cast<float2*>(cgw_s);
        #pragma unroll 4
        for (int i = tid; i < wtp::NNZ * wtp::NCHP; i += wtp::NTHREADS) {
            const int t  = i >> 3;       // term, REFERENCE order
            const int pc = i & 7;        // channel-pair
            const float cgv = __ldg(cg + t);
            const int   li  = __ldg(l_ind + t);
            const float2 wv =
                *reinterpret_cast<const float2*>(w + li * wtp::C + cbase + pc * 2);
            // scatter into [pc][sorted_slot]
            cgw_f[pc * wtp::NNZ + wtp::INV_c.slot[t]] =
                make_float2(cgv * wv.x, cgv * wv.y);
        }
    }
    __syncthreads();

    const int row0 = rowbase + rs;
    const int row1 = row0 + wtp::NSLOT;
    const size_t base0 = (size_t)row0 * wtp::MOUT * wtp::C + cbase + cp * 2;
    const size_t base1 = (size_t)row1 * wtp::MOUT * wtp::C + cbase + cp * 2;
    const ull* x1p0 = reinterpret_cast<const ull*>(x1 + base0);
    const ull* x2p0 = reinterpret_cast<const ull*>(x2 + base0);
    const ull* x1p1 = reinterpret_cast<const ull*>(x1 + base1);
    const ull* x2p1 = reinterpret_cast<const ull*>(x2 + base1);
    ull* op0 = reinterpret_cast<ull*>(out + base0);
    ull* op1 = reinterpret_cast<ull*>(out + base1);

    ull X1[wtp::RPT][wtp::MOUT], X2[wtp::RPT][wtp::MOUT];
    #pragma unroll
    for (int m = 0; m < wtp::MOUT; m++) {
        constexpr int CC = wtp::C / 2;
        X1[0][m] = x1p0[m * CC];
        X2[0][m] = x2p0[m * CC];
        X1[1][m] = x1p1[m * CC];
        X2[1][m] = x2p1[m * CC];
    }

    const ull* cgw_tp = cgw_s + cp * wtp::NNZ;
    run_group<0>(cgw_tp, X1, X2, op0, op1);
    run_group<1>(cgw_tp, X1, X2, op0, op1);
    run_group<2>(cgw_tp, X1, X2, op0, op1);
    run_group<3>(cgw_tp, X1, X2, op0, op1);
    run_group<4>(cgw_tp, X1, X2, op0, op1);
    run_group<5>(cgw_tp, X1, X2, op0, op1);
    run_group<6>(cgw_tp, X1, X2, op0, op1);
}

// ============================================================================
// Launch. Inputs (metadata order): x1, x2, weight, CG_vals, M1, M2, l_ind, M_seg
// ============================================================================
extern "C" void kernel_launch(void* const* d_in, const int* in_sizes, int n_in,
                              void* d_out, int out_size)
{
    const float* x1    = (const float*)d_in[0];
    const float* x2    = (const float*)d_in[1];
    const float* w     = (const float*)d_in[2];
    const float* cg    = (const float*)d_in[3];
    const int*   l_ind = (const int*)d_in[6];
    float*       out   = (float*)d_out;

    const int B = in_sizes[0] / (wtp::MOUT * wtp::C);   // 2048
    const int smem = wtp::NNZ * wtp::NCHP * 8;          // 30592 bytes

    cudaFuncSetAttribute(wtp_kernel, cudaFuncAttributeMaxDynamicSharedMemorySize, smem);

    const int grid = (B / wtp::NROWB) * (wtp::C / 16);  // 128 * 8 = 1024
    wtp_kernel<<<grid, wtp::NTHREADS, smem>>>(x1, x2, w, cg, l_ind, out);
}

// round 6
// speedup vs baseline: 1.1847x; 1.1847x over previous
#include <cuda_runtime.h>
#include <cstdint>
#include <utility>

// ============================================================================
// Compile-time structure builder. Reproduces the reference enumeration exactly
// (to recover each term's original index into CG_vals), then re-sorts terms:
//   major: m_total = m1+m2  (7 groups, -3..3)
//   mid:   (M1, M2) pair    (pair products factorized)
//   minor: l (output degree) -> accumulator slot l - |m|
// cgw shared layout is PAIR-INTERLEAVED: slot s, channel-pair cp lives at
// ull index (s/2)*16 + cp*2 + (s&1), so one LDS.128 per cp feeds 2 terms and
// a warp's 8 cp lanes read one contiguous 128-B chunk (1 wavefront).
// ============================================================================
namespace wtp {

constexpr int LMAX = 3;
constexpr int MOUT = 16;
constexpr int NNZ  = 478;
constexpr int C    = 128;
constexpr int NCHP = 8;          // channel-pairs per block (16 channels)
constexpr int NSLOT = 16;        // row slots per block
constexpr int RPT  = 2;          // rows per thread
constexpr int NROWB = NSLOT * RPT;       // 32 rows per block
constexpr int NTHREADS = NCHP * NSLOT;   // 128
constexpr int NGRP = 7;

struct Structure {
    int m1[NNZ];
    int m2[NNZ];
    int aidx[NNZ];
    int orig[NNZ];
    bool newpair[NNZ];
    int start[NGRP + 1];
    int count;
};

constexpr Structure build_structure() {
    Structure s{};
    int tl[64] = {}, tl1[64] = {}, tl2[64] = {};
    int nt = 0;
    for (int l1 = 0; l1 <= LMAX; l1++)
        for (int l2 = 0; l2 <= LMAX; l2++) {
            int lo = (l1 > l2) ? (l1 - l2) : (l2 - l1);
            int hi = (l1 + l2 < LMAX) ? (l1 + l2) : LMAX;
            for (int l = lo; l <= hi; l++) { tl[nt]=l; tl1[nt]=l1; tl2[nt]=l2; nt++; }
        }
    int rm1[NNZ]={}, rm2[NNZ]={}, rl[NNZ]={}, rm[NNZ]={};
    int cnt = 0;
    for (int l = 0; l <= LMAX; l++)
        for (int m = -l; m <= l; m++) {
            for (int t = 0; t < nt; t++) {
                if (tl[t] != l) continue;
                int l1 = tl1[t], l2 = tl2[t];
                int lo = (-l1 > m - l2) ? -l1 : (m - l2);
                int hi = (l1 < m + l2) ? l1 : (m + l2);
                for (int m1 = lo; m1 <= hi; m1++) {
                    int m2 = m - m1;
                    rm1[cnt] = l1*l1 + l1 + m1;
                    rm2[cnt] = l2*l2 + l2 + m2;
                    rl[cnt]  = l;
                    rm[cnt]  = m;
                    cnt++;
                }
            }
        }
    s.count = cnt;
    int key[NNZ] = {};
    for (int i = 0; i < cnt; i++)
        key[i] = (((rm[i] + 3) * 16 + rm1[i]) * 16 + rm2[i]) * 4 + rl[i];
    int sm[NNZ] = {};
    for (int i = 0; i < cnt; i++) {
        int rank = 0;
        for (int j = 0; j < cnt; j++)
            if (key[j] < key[i] || (key[j] == key[i] && j < i)) rank++;
        int am = rm[i] < 0 ? -rm[i] : rm[i];
        s.m1[rank]   = rm1[i];
        s.m2[rank]   = rm2[i];
        s.aidx[rank] = rl[i] - am;
        s.orig[rank] = i;
        sm[rank]     = rm[i];
    }
    for (int i = 0; i < cnt; i++)
        s.newpair[i] = (i == 0) || (s.m1[i] != s.m1[i-1]) || (s.m2[i] != s.m2[i-1]);
    for (int g = 0; g <= NGRP; g++) {
        int st = cnt;
        for (int i = 0; i < cnt; i++)
            if (sm[i] + 3 >= g) { st = i; break; }
        s.start[g] = st;
    }
    return s;
}

constexpr Structure S = build_structure();
static_assert(S.count == NNZ, "term count mismatch vs reference structure");
static_assert(S.start[0] == 0 && S.start[NGRP] == NNZ, "group partition broken");

// sorted slot for each reference index; lives in constant memory because the
// build loop indexes it with a runtime term index.
struct Inv { int slot[NNZ]; };
constexpr Inv build_inv() {
    Inv v{};
    for (int t = 0; t < NNZ; t++) v.slot[S.orig[t]] = t;
    return v;
}
__constant__ Inv INV_c = build_inv();

// ull index of (sorted slot s, channel pair cp) in the interleaved cgw table
__host__ __device__ constexpr int cgw_idx(int s, int cp) {
    return (s >> 1) * (2 * NCHP) + cp * 2 + (s & 1);
}

} // namespace wtp

using ull = unsigned long long;

// ============================================================================
// Per-term executor with preloaded wv. Packed f32x2, 2 rows per thread.
// ============================================================================
template <int T>
__device__ __forceinline__ void do_term_wv(
    const ull wv,
    const ull (&X1)[wtp::RPT][wtp::MOUT],
    const ull (&X2)[wtp::RPT][wtp::MOUT],
    ull (&ACC)[wtp::RPT][4],
    ull (&p)[wtp::RPT])
{
    constexpr int m1 = wtp::S.m1[T];
    constexpr int m2 = wtp::S.m2[T];
    constexpr int ai = wtp::S.aidx[T];
    if constexpr (wtp::S.newpair[T]) {
        asm("mul.rn.f32x2 %0, %1, %2;" : "=l"(p[0]) : "l"(X1[0][m1]), "l"(X2[0][m2]));
        asm("mul.rn.f32x2 %0, %1, %2;" : "=l"(p[1]) : "l"(X1[1][m1]), "l"(X2[1][m2]));
    }
    asm("fma.rn.f32x2 %0, %1, %2, %3;" : "=l"(ACC[0][ai]) : "l"(p[0]), "l"(wv), "l"(ACC[0][ai]));
    asm("fma.rn.f32x2 %0, %1, %2, %3;" : "=l"(ACC[1][ai]) : "l"(p[1]), "l"(wv), "l"(ACC[1][ai]));
}

// One LDS.128 feeds two consecutive sorted terms (slots 2P, 2P+1).
template <int PB, int... Is>
__device__ __forceinline__ void run_pairs(
    std::integer_sequence<int, Is...>,
    const ull* __restrict__ cgw_cp,   // = cgw_s + cp*2
    const ull (&X1)[wtp::RPT][wtp::MOUT],
    const ull (&X2)[wtp::RPT][wtp::MOUT],
    ull (&ACC)[wtp::RPT][4],
    ull (&p)[wtp::RPT])
{
    (([&] {
        constexpr int P = PB + Is;                  // pair index
        const ulonglong2 wv2 =
            *reinterpret_cast<const ulonglong2*>(cgw_cp + P * 16);
        do_term_wv<2 * P>(wv2.x, X1, X2, ACC, p);
        do_term_wv<2 * P + 1>(wv2.y, X1, X2, ACC, p);
    }()), ...);
}

template <int G>
__device__ __forceinline__ void run_group(
    const ull* __restrict__ cgw_cp,   // = cgw_s + cp*2
    const ull (&X1)[wtp::RPT][wtp::MOUT],
    const ull (&X2)[wtp::RPT][wtp::MOUT],
    ull* __restrict__ op0,
    ull* __restrict__ op1)
{
    constexpr int m  = G - 3;
    constexpr int la = m < 0 ? -m : m;
    constexpr int ns = 4 - la;
    constexpr int nb = wtp::S.start[G];
    constexpr int ne = wtp::S.start[G + 1];
    constexpr int first = (nb & 1) ? nb + 1 : nb;   // even slot = pair base
    constexpr int npair = (ne - first) / 2;
    constexpr int tail  = first + 2 * npair;        // == ne or ne-1

    ull ACC[wtp::RPT][4] = {};
    ull p[wtp::RPT] = {};

    if constexpr (nb & 1)
        do_term_wv<nb>(cgw_cp[(nb >> 1) * 16 + 1], X1, X2, ACC, p);
    run_pairs<first / 2>(std::make_integer_sequence<int, npair>{},
                         cgw_cp, X1, X2, ACC, p);
    if constexpr (tail < ne)
        do_term_wv<tail>(cgw_cp[(tail >> 1) * 16], X1, X2, ACC, p);

    #pragma unroll
    for (int i = 0; i < ns; i++) {
        constexpr int CC = wtp::C / 2;
        const int l = la + i;
        op0[(l * l + l + m) * CC] = ACC[0][i];
        op1[(l * l + l + m) * CC] = ACC[1][i];
    }
}

// ============================================================================
// Kernel. Block = 128 threads = 8 ch-pairs x 16 row-slots; each thread owns
// 2 rows (rs, rs+16) -> 16 channels x 32 rows per block. Grid = 512.
// Shared cgw: 478*8 ull = 30592 B, pair-interleaved. 3 blocks/SM.
// ============================================================================
__global__ void __launch_bounds__(wtp::NTHREADS, 3)
wtp_kernel(const float* __restrict__ x1,
           const float* __restrict__ x2,
           const float* __restrict__ w,
           const float* __restrict__ cg,
           const int*   __restrict__ l_ind,
           float* __restrict__ out)
{
    extern __shared__ ull cgw_s[];  // pair-interleaved, 478*8 entries

    const int tid     = threadIdx.x;
    const int cgroup  = blockIdx.x & 7;                  // 8 groups of 16 channels
    const int rowbase = (blockIdx.x >> 3) * wtp::NROWB;  // 32 rows per block
    const int cp      = tid & (wtp::NCHP - 1);
    const int rs      = tid >> 3;                        // 0..15
    const int cbase   = cgroup * 16;

    // --- per-block CG*weight table (coalesced loads; interleaved STS) ---
    {
        float2* cgw_f = reinterpret_cast<float2*>(cgw_s);
        #pragma unroll 4
        for (int i = tid; i < wtp::NNZ * wtp::NCHP; i += wtp::NTHREADS) {
            const int t  = i >> 3;       // term, REFERENCE order
            const int pc = i & 7;        // channel-pair
            const float cgv = __ldg(cg + t);
            const int   li  = __ldg(l_ind + t);
            const float2 wv =
                *reinterpret_cast<const float2*>(w + li * wtp::C + cbase + pc * 2);
            cgw_f[wtp::cgw_idx(wtp::INV_c.slot[t], pc)] =
                make_float2(cgv * wv.x, cgv * wv.y);
        }
    }
    __syncthreads();

    const int row0 = rowbase + rs;
    const int row1 = row0 + wtp::NSLOT;
    const size_t base0 = (size_t)row0 * wtp::MOUT * wtp::C + cbase + cp * 2;
    const size_t base1 = (size_t)row1 * wtp::MOUT * wtp::C + cbase + cp * 2;
    const ull* x1p0 = reinterpret_cast<const ull*>(x1 + base0);
    const ull* x2p0 = reinterpret_cast<const ull*>(x2 + base0);
    const ull* x1p1 = reinterpret_cast<const ull*>(x1 + base1);
    const ull* x2p1 = reinterpret_cast<const ull*>(x2 + base1);
    ull* op0 = reinterpret_cast<ull*>(out + base0);
    ull* op1 = reinterpret_cast<ull*>(out + base1);

    ull X1[wtp::RPT][wtp::MOUT], X2[wtp::RPT][wtp::MOUT];
    #pragma unroll
    for (int m = 0; m < wtp::MOUT; m++) {
        constexpr int CC = wtp::C / 2;
        X1[0][m] = x1p0[m * CC];
        X2[0][m] = x2p0[m * CC];
        X1[1][m] = x1p1[m * CC];
        X2[1][m] = x2p1[m * CC];
    }

    const ull* cgw_cp = cgw_s + cp * 2;
    run_group<0>(cgw_cp, X1, X2, op0, op1);
    run_group<1>(cgw_cp, X1, X2, op0, op1);
    run_group<2>(cgw_cp, X1, X2, op0, op1);
    run_group<3>(cgw_cp, X1, X2, op0, op1);
    run_group<4>(cgw_cp, X1, X2, op0, op1);
    run_group<5>(cgw_cp, X1, X2, op0, op1);
    run_group<6>(cgw_cp, X1, X2, op0, op1);
}

// ============================================================================
// Launch. Inputs (metadata order): x1, x2, weight, CG_vals, M1, M2, l_ind, M_seg
// ============================================================================
extern "C" void kernel_launch(void* const* d_in, const int* in_sizes, int n_in,
                              void* d_out, int out_size)
{
    const float* x1    = (const float*)d_in[0];
    const float* x2    = (const float*)d_in[1];
    const float* w     = (const float*)d_in[2];
    const float* cg    = (const float*)d_in[3];
    const int*   l_ind = (const int*)d_in[6];
    float*       out   = (float*)d_out;

    const int B = in_sizes[0] / (wtp::MOUT * wtp::C);   // 2048
    const int smem = wtp::NNZ * wtp::NCHP * 8;          // 30592 bytes

    cudaFuncSetAttribute(wtp_kernel, cudaFuncAttributeMaxDynamicSharedMemorySize, smem);

    const int grid = (B / wtp::NROWB) * (wtp::C / 16);  // 64 * 8 = 512
    wtp_kernel<<<grid, wtp::NTHREADS, smem>>>(x1, x2, w, cg, l_ind, out);
}